// round 5
// baseline (speedup 1.0000x reference)
#include <cuda_runtime.h>
#include <cuda_bf16.h>
#include <math.h>
#include <cstdint>

#define B_ 64
#define H_ 1024

// ---------------------------------------------------------------------------
// Scratch (__device__ globals; allocation-free rule)
// ---------------------------------------------------------------------------
__device__ float g_s[9][B_ * H_];   // 9 pre-activations (fp32)
__device__ float g_ep[8][B_ * H_];  // split-K partials of e = k_t @ We

// ---------------------------------------------------------------------------
// helpers
// ---------------------------------------------------------------------------
__device__ __forceinline__ uint32_t smem_u32(const void* p) {
    uint32_t a;
    asm("{ .reg .u64 t; cvta.to.shared.u64 t, %1; cvt.u32.u64 %0, t; }" : "=r"(a) : "l"(p));
    return a;
}

// split two fp32 into bf16-hi pair and bf16-lo (residual) pair
__device__ __forceinline__ void split2(float v0, float v1, uint32_t& hi, uint32_t& lo) {
    __nv_bfloat16 h0 = __float2bfloat16_rn(v0);
    __nv_bfloat16 h1 = __float2bfloat16_rn(v1);
    float l0 = v0 - __bfloat162float(h0);
    float l1 = v1 - __bfloat162float(h1);
    __nv_bfloat162 hp; hp.x = h0; hp.y = h1;
    __nv_bfloat162 lp = __floats2bfloat162_rn(l0, l1);
    hi = *(uint32_t*)&hp;
    lo = *(uint32_t*)&lp;
}

#define LDSM_X4(r0, r1, r2, r3, addr) \
    asm volatile("ldmatrix.sync.aligned.m8n8.x4.shared.b16 {%0,%1,%2,%3}, [%4];" \
        : "=r"(r0), "=r"(r1), "=r"(r2), "=r"(r3) : "r"(addr))
#define LDSM_X2T(r0, r1, addr) \
    asm volatile("ldmatrix.sync.aligned.m8n8.x2.trans.shared.b16 {%0,%1}, [%2];" \
        : "=r"(r0), "=r"(r1) : "r"(addr))
#define MMA16816(c, a0, a1, a2, a3, b0, b1) \
    asm volatile("mma.sync.aligned.m16n8k16.row.col.f32.bf16.bf16.f32 " \
        "{%0,%1,%2,%3}, {%4,%5,%6,%7}, {%8,%9}, {%0,%1,%2,%3};" \
        : "+f"(c[0]), "+f"(c[1]), "+f"(c[2]), "+f"(c[3]) \
        : "r"(a0), "r"(a1), "r"(a2), "r"(a3), "r"(b0), "r"(b1))

// ---------------------------------------------------------------------------
// Kernel 1: 9 GEMM jobs on HMMA (mma.sync bf16, 3-term error-compensated).
// M=64, N=64/CTA, K=1024. grid (16 ntiles, 9 jobs), 128 threads.
// jobs: 0,1 = i (x-half, h-half); 2,3 = f; 4,5 = o; 6 = k; 7 = v; 8 = q
// Fp32 W/A loaded from gmem, split to bf16 hi/lo in-kernel (no convert pass).
// smem per stage: Ah | Al | Wh | Wl, each [64][72] bf16 (144 B row stride)
// ---------------------------------------------------------------------------
#define ROWB 144                    // 72 bf16 per row
#define OFF_AH 0
#define OFF_AL 9216
#define OFF_WH 18432
#define OFF_WL 27648
#define STG    36864
#define SMEM_TOTAL (2 * STG)        // 73728 B

__global__ __launch_bounds__(128, 1) void mma_kernel(
    const float* __restrict__ x, const float* __restrict__ h,
    const float* __restrict__ Wi, const float* __restrict__ Wf,
    const float* __restrict__ Wo, const float* __restrict__ Wk,
    const float* __restrict__ Wv, const float* __restrict__ Wq)
{
    extern __shared__ __align__(16) char smem[];
    const uint32_t sb = smem_u32(smem);
    const int tid = threadIdx.x;
    const int wid = tid >> 5;
    const int lane = tid & 31;
    const int job = blockIdx.y;
    const int n0 = blockIdx.x * 64;

    const float *A, *W;
    switch (job) {
        case 0: A = x; W = Wi;                          break;
        case 1: A = h; W = Wi + (size_t)1024 * 1024;    break;
        case 2: A = x; W = Wf;                          break;
        case 3: A = h; W = Wf + (size_t)1024 * 1024;    break;
        case 4: A = x; W = Wo;                          break;
        case 5: A = h; W = Wo + (size_t)1024 * 1024;    break;
        case 6: A = x; W = Wk;                          break;
        case 7: A = x; W = Wv;                          break;
        default: A = h; W = Wq;                         break;
    }
    float* out = g_s[job];

    // gmem load mapping: 128 threads cover a 64x64 fp32 tile
    const int lrow = tid >> 1;             // 0..63
    const int lcb  = (tid & 1) * 32;       // col base within 64

    // ldmatrix source addresses
    const int am   = (lane & 15);          // A row within warp tile
    const int akoff = (lane >> 4) * 8;     // 0 or 8 (k offset)
    const int m0   = wid * 16;
    const uint32_t a_off = (uint32_t)(m0 + am) * ROWB + (uint32_t)akoff * 2;
    const uint32_t b_off = (uint32_t)(lane & 15) * ROWB;

    float acc[8][4] = {};
    float4 pA[8], pW[8];

    // ---- prologue: load chunk 0 ----
    #pragma unroll
    for (int j = 0; j < 8; j++) {
        pA[j] = *(const float4*)(A + (size_t)lrow * H_ + lcb + j * 4);
        pW[j] = *(const float4*)(W + (size_t)lrow * H_ + n0 + lcb + j * 4);
    }
    {
        char* st = smem;
        #pragma unroll
        for (int j = 0; j < 8; j++) {
            const uint32_t co = (uint32_t)(lcb + j * 4) * 2;
            uint32_t h0, l0, h1, l1;
            split2(pA[j].x, pA[j].y, h0, l0);
            split2(pA[j].z, pA[j].w, h1, l1);
            *(uint2*)(st + OFF_AH + lrow * ROWB + co) = make_uint2(h0, h1);
            *(uint2*)(st + OFF_AL + lrow * ROWB + co) = make_uint2(l0, l1);
            split2(pW[j].x, pW[j].y, h0, l0);
            split2(pW[j].z, pW[j].w, h1, l1);
            *(uint2*)(st + OFF_WH + lrow * ROWB + co) = make_uint2(h0, h1);
            *(uint2*)(st + OFF_WL + lrow * ROWB + co) = make_uint2(l0, l1);
        }
    }
    __syncthreads();

    #pragma unroll 1
    for (int t = 0; t < 16; t++) {
        const int s = t & 1;

        // prefetch next chunk into registers
        if (t < 15) {
            const int k0 = (t + 1) * 64;
            #pragma unroll
            for (int j = 0; j < 8; j++) {
                pA[j] = *(const float4*)(A + (size_t)lrow * H_ + k0 + lcb + j * 4);
                pW[j] = *(const float4*)(W + (size_t)(k0 + lrow) * H_ + n0 + lcb + j * 4);
            }
        }

        // compute on stage s
        {
            const uint32_t ah = sb + s * STG + OFF_AH + a_off;
            const uint32_t al = sb + s * STG + OFF_AL + a_off;
            const uint32_t wh = sb + s * STG + OFF_WH + b_off;
            const uint32_t wl = sb + s * STG + OFF_WL + b_off;
            #pragma unroll
            for (int ks = 0; ks < 4; ks++) {
                const uint32_t ko2 = ks * 32;          // kk*2 bytes (kk=ks*16)
                const uint32_t kor = ks * 16 * ROWB;   // kk rows for B
                uint32_t a0, a1, a2, a3, e0, e1, e2, e3;
                LDSM_X4(a0, a1, a2, a3, ah + ko2);
                LDSM_X4(e0, e1, e2, e3, al + ko2);
                #pragma unroll
                for (int na = 0; na < 8; na++) {
                    const uint32_t no = na * 16;       // nn*2 bytes
                    uint32_t b0, b1, f0, f1;
                    LDSM_X2T(b0, b1, wh + kor + no);
                    LDSM_X2T(f0, f1, wl + kor + no);
                    MMA16816(acc[na], a0, a1, a2, a3, b0, b1);
                    MMA16816(acc[na], a0, a1, a2, a3, f0, f1);
                    MMA16816(acc[na], e0, e1, e2, e3, b0, b1);
                }
            }
        }

        // convert + store next chunk into the other stage
        if (t < 15) {
            char* st = smem + (s ^ 1) * STG;
            #pragma unroll
            for (int j = 0; j < 8; j++) {
                const uint32_t co = (uint32_t)(lcb + j * 4) * 2;
                uint32_t h0, l0, h1, l1;
                split2(pA[j].x, pA[j].y, h0, l0);
                split2(pA[j].z, pA[j].w, h1, l1);
                *(uint2*)(st + OFF_AH + lrow * ROWB + co) = make_uint2(h0, h1);
                *(uint2*)(st + OFF_AL + lrow * ROWB + co) = make_uint2(l0, l1);
                split2(pW[j].x, pW[j].y, h0, l0);
                split2(pW[j].z, pW[j].w, h1, l1);
                *(uint2*)(st + OFF_WH + lrow * ROWB + co) = make_uint2(h0, h1);
                *(uint2*)(st + OFF_WL + lrow * ROWB + co) = make_uint2(l0, l1);
            }
        }
        __syncthreads();
    }

    // epilogue: fragment layout -> g_s[job]
    const int r0 = wid * 16 + (lane >> 2);
    const int c0 = (lane & 3) * 2;
    #pragma unroll
    for (int na = 0; na < 8; na++) {
        *(float2*)(out + (size_t)r0 * H_ + n0 + na * 8 + c0) =
            make_float2(acc[na][0], acc[na][1]);
        *(float2*)(out + (size_t)(r0 + 8) * H_ + n0 + na * 8 + c0) =
            make_float2(acc[na][2], acc[na][3]);
    }
}

// ---------------------------------------------------------------------------
// Kernel 2: e partials. A = (g_s[6] + bk) [64,1024], W = We. split-K=8.
// ---------------------------------------------------------------------------
__global__ __launch_bounds__(256, 1) void egemm_kernel(
    const float* __restrict__ We, const float* __restrict__ bk)
{
    constexpr int TK = 32;
    __shared__ __align__(16) float As[2][TK][64 + 4];
    __shared__ __align__(16) float Ws[2][TK][64 + 4];

    const float* A0 = &g_s[6][0];
    float* out = &g_ep[blockIdx.y][0];
    const int kbase = blockIdx.y * 128;
    const int n0 = blockIdx.x * 64;
    const int t  = threadIdx.x;
    const int tr = t >> 4;
    const int tc = t & 15;

    const int arow = t >> 3;
    const int akq  = (t & 7) << 2;
    const int wr   = t >> 4;
    const int wc   = (t & 15) << 2;

    float acc[4][4] = {};
    float4 pa0, pa1, pw0, pw1, pb;

    pa0 = *(const float4*)(A0 + arow * H_ + kbase + akq);
    pa1 = *(const float4*)(A0 + (arow + 32) * H_ + kbase + akq);
    pb  = *(const float4*)(bk + kbase + akq);
    pw0 = *(const float4*)(We + (size_t)(kbase + wr) * H_ + n0 + wc);
    pw1 = *(const float4*)(We + (size_t)(kbase + wr + 16) * H_ + n0 + wc);
    As[0][akq + 0][arow] = pa0.x + pb.x;  As[0][akq + 1][arow] = pa0.y + pb.y;
    As[0][akq + 2][arow] = pa0.z + pb.z;  As[0][akq + 3][arow] = pa0.w + pb.w;
    As[0][akq + 0][arow + 32] = pa1.x + pb.x;  As[0][akq + 1][arow + 32] = pa1.y + pb.y;
    As[0][akq + 2][arow + 32] = pa1.z + pb.z;  As[0][akq + 3][arow + 32] = pa1.w + pb.w;
    *(float4*)&Ws[0][wr][wc]      = pw0;
    *(float4*)&Ws[0][wr + 16][wc] = pw1;
    __syncthreads();

    #pragma unroll 1
    for (int tile = 0; tile < 4; tile++) {
        const int cur = tile & 1;
        const int nxt = cur ^ 1;
        if (tile + 1 < 4) {
            const int k0n = kbase + (tile + 1) * TK;
            pa0 = *(const float4*)(A0 + arow * H_ + k0n + akq);
            pa1 = *(const float4*)(A0 + (arow + 32) * H_ + k0n + akq);
            pb  = *(const float4*)(bk + k0n + akq);
            pw0 = *(const float4*)(We + (size_t)(k0n + wr) * H_ + n0 + wc);
            pw1 = *(const float4*)(We + (size_t)(k0n + wr + 16) * H_ + n0 + wc);
        }
        #pragma unroll
        for (int kk = 0; kk < TK; kk++) {
            float4 a = *(const float4*)&As[cur][kk][tr << 2];
            float4 b = *(const float4*)&Ws[cur][kk][tc << 2];
            #pragma unroll
            for (int i = 0; i < 4; i++) {
                float av = (i == 0) ? a.x : (i == 1) ? a.y : (i == 2) ? a.z : a.w;
                acc[i][0] = fmaf(av, b.x, acc[i][0]);
                acc[i][1] = fmaf(av, b.y, acc[i][1]);
                acc[i][2] = fmaf(av, b.z, acc[i][2]);
                acc[i][3] = fmaf(av, b.w, acc[i][3]);
            }
        }
        if (tile + 1 < 4) {
            As[nxt][akq + 0][arow] = pa0.x + pb.x;  As[nxt][akq + 1][arow] = pa0.y + pb.y;
            As[nxt][akq + 2][arow] = pa0.z + pb.z;  As[nxt][akq + 3][arow] = pa0.w + pb.w;
            As[nxt][akq + 0][arow + 32] = pa1.x + pb.x;  As[nxt][akq + 1][arow + 32] = pa1.y + pb.y;
            As[nxt][akq + 2][arow + 32] = pa1.z + pb.z;  As[nxt][akq + 3][arow + 32] = pa1.w + pb.w;
            *(float4*)&Ws[nxt][wr][wc]      = pw0;
            *(float4*)&Ws[nxt][wr + 16][wc] = pw1;
        }
        __syncthreads();
    }

    #pragma unroll
    for (int i = 0; i < 4; i++) {
        int row = (tr << 2) + i;
        float4 v = make_float4(acc[i][0], acc[i][1], acc[i][2], acc[i][3]);
        *(float4*)(out + row * H_ + n0 + (tc << 2)) = v;
    }
}

// ---------------------------------------------------------------------------
// Kernel 3: C-stream update (HBM roofline pass)
// ---------------------------------------------------------------------------
__device__ __forceinline__ float sigmoidf_(float z) {
    return 1.0f / (1.0f + expf(-z));
}

__global__ __launch_bounds__(256, 8) void update_kernel(
    const float* __restrict__ C_prev, const float* __restrict__ n_prev,
    const float* __restrict__ bi, const float* __restrict__ bf,
    const float* __restrict__ bo, const float* __restrict__ bk,
    const float* __restrict__ bv, const float* __restrict__ bq,
    const float* __restrict__ be,
    float* __restrict__ out_h, float* __restrict__ out_C,
    float* __restrict__ out_n)
{
    __shared__ __align__(16) float ks[H_];
    __shared__ __align__(16) float qs[H_];

    const int b    = blockIdx.y;
    const int r0   = blockIdx.x * 8;
    const int t    = threadIdx.x;
    const int w    = t >> 5;
    const int lane = t & 31;

    {
        int c = t << 2;
        float4 k0 = *(const float4*)(&g_s[6][b * H_] + c);
        float4 bkv = *(const float4*)(bk + c);
        float4 q0 = *(const float4*)(&g_s[8][b * H_] + c);
        float4 bqv = *(const float4*)(bq + c);
        *(float4*)&ks[c] = make_float4(k0.x + bkv.x, k0.y + bkv.y,
                                       k0.z + bkv.z, k0.w + bkv.w);
        *(float4*)&qs[c] = make_float4(q0.x + bqv.x, q0.y + bqv.y,
                                       q0.z + bqv.z, q0.w + bqv.w);
    }
    __syncthreads();

    const int r = r0 + w;
    const int br = b * H_ + r;

    const float it = sigmoidf_(g_s[0][br] + g_s[1][br] + bi[r]);
    const float ft = sigmoidf_(g_s[2][br] + g_s[3][br] + bf[r]);
    const float ot = sigmoidf_(g_s[4][br] + g_s[5][br] + bo[r]);
    const float vt = g_s[7][br] + bv[r];
    const float iv = it * vt;

    const size_t base = (size_t)b * H_ * H_ + (size_t)r * H_;
    float dot = 0.0f;

    #pragma unroll
    for (int it8 = 0; it8 < 8; it8++) {
        int c = (lane << 2) + (it8 << 7);
        float4 cp = __ldcs((const float4*)(C_prev + base + c));
        float4 kv = *(const float4*)&ks[c];
        float4 qv = *(const float4*)&qs[c];
        float4 ct;
        ct.x = fmaf(ft, cp.x, iv * kv.x);
        ct.y = fmaf(ft, cp.y, iv * kv.y);
        ct.z = fmaf(ft, cp.z, iv * kv.z);
        ct.w = fmaf(ft, cp.w, iv * kv.w);
        __stcs((float4*)(out_C + base + c), ct);
        dot = fmaf(ct.x, qv.x, dot);
        dot = fmaf(ct.y, qv.y, dot);
        dot = fmaf(ct.z, qv.z, dot);
        dot = fmaf(ct.w, qv.w, dot);
    }

    #pragma unroll
    for (int off = 16; off; off >>= 1)
        dot += __shfl_xor_sync(0xffffffffu, dot, off);

    if (lane == 0) {
        float e = be[r];
        #pragma unroll
        for (int p = 0; p < 8; p++) e += g_ep[p][br];
        float nt = fmaf(ft, n_prev[br], it * expf(e));
        out_n[br] = nt;
        out_h[br] = ot * dot / nt;
    }
}

// ---------------------------------------------------------------------------
extern "C" void kernel_launch(void* const* d_in, const int* in_sizes, int n_in,
                              void* d_out, int out_size)
{
    const float* x      = (const float*)d_in[0];
    const float* h_prev = (const float*)d_in[1];
    const float* C_prev = (const float*)d_in[2];
    const float* n_prev = (const float*)d_in[3];
    const float* Wi = (const float*)d_in[4];
    const float* bi = (const float*)d_in[5];
    const float* Wf = (const float*)d_in[6];
    const float* bf = (const float*)d_in[7];
    const float* Wo = (const float*)d_in[8];
    const float* bo = (const float*)d_in[9];
    const float* Wk = (const float*)d_in[10];
    const float* bk = (const float*)d_in[11];
    const float* Wv = (const float*)d_in[12];
    const float* bv = (const float*)d_in[13];
    const float* Wq = (const float*)d_in[14];
    const float* bq = (const float*)d_in[15];
    const float* We = (const float*)d_in[16];
    const float* be = (const float*)d_in[17];

    float* out_h = (float*)d_out;
    float* out_C = out_h + B_ * H_;
    float* out_n = out_C + (size_t)B_ * H_ * H_;

    static int smem_set = 0;
    if (!smem_set) {
        cudaFuncSetAttribute(mma_kernel, cudaFuncAttributeMaxDynamicSharedMemorySize,
                             SMEM_TOTAL);
        smem_set = 1;
    }

    mma_kernel<<<dim3(16, 9), 128, SMEM_TOTAL>>>(x, h_prev, Wi, Wf, Wo, Wk, Wv, Wq);
    egemm_kernel<<<dim3(16, 8), 256>>>(We, bk);
    update_kernel<<<dim3(128, 64), 256>>>(C_prev, n_prev, bi, bf, bo, bk, bv, bq, be,
                                          out_h, out_C, out_n);
}

// round 6
// speedup vs baseline: 1.0405x; 1.0405x over previous
#include <cuda_runtime.h>
#include <cuda_bf16.h>
#include <math.h>
#include <cstdint>

#define B_ 64
#define H_ 1024

// ---------------------------------------------------------------------------
// Scratch (__device__ globals; allocation-free rule)
// ---------------------------------------------------------------------------
__device__ float g_s[9][B_ * H_];   // 9 pre-activations (fp32)
__device__ float g_ep[8][B_ * H_];  // split-K partials of e = k_t @ We

// ---------------------------------------------------------------------------
// helpers
// ---------------------------------------------------------------------------
__device__ __forceinline__ uint32_t smem_u32(const void* p) {
    uint32_t a;
    asm("{ .reg .u64 t; cvta.to.shared.u64 t, %1; cvt.u32.u64 %0, t; }" : "=r"(a) : "l"(p));
    return a;
}

// split two fp32 into bf16-hi pair and bf16-lo (residual) pair
__device__ __forceinline__ void split2(float v0, float v1, uint32_t& hi, uint32_t& lo) {
    __nv_bfloat16 h0 = __float2bfloat16_rn(v0);
    __nv_bfloat16 h1 = __float2bfloat16_rn(v1);
    float l0 = v0 - __bfloat162float(h0);
    float l1 = v1 - __bfloat162float(h1);
    __nv_bfloat162 hp; hp.x = h0; hp.y = h1;
    __nv_bfloat162 lp = __floats2bfloat162_rn(l0, l1);
    hi = *(uint32_t*)&hp;
    lo = *(uint32_t*)&lp;
}

#define LDSM_X4(r0, r1, r2, r3, addr) \
    asm volatile("ldmatrix.sync.aligned.m8n8.x4.shared.b16 {%0,%1,%2,%3}, [%4];" \
        : "=r"(r0), "=r"(r1), "=r"(r2), "=r"(r3) : "r"(addr))
#define LDSM_X4T(r0, r1, r2, r3, addr) \
    asm volatile("ldmatrix.sync.aligned.m8n8.x4.trans.shared.b16 {%0,%1,%2,%3}, [%4];" \
        : "=r"(r0), "=r"(r1), "=r"(r2), "=r"(r3) : "r"(addr))
#define MMA16816(c, a0, a1, a2, a3, b0, b1) \
    asm volatile("mma.sync.aligned.m16n8k16.row.col.f32.bf16.bf16.f32 " \
        "{%0,%1,%2,%3}, {%4,%5,%6,%7}, {%8,%9}, {%0,%1,%2,%3};" \
        : "+f"(c[0]), "+f"(c[1]), "+f"(c[2]), "+f"(c[3]) \
        : "r"(a0), "r"(a1), "r"(a2), "r"(a3), "r"(b0), "r"(b1))

// ---------------------------------------------------------------------------
// Kernel 1: 9 GEMM jobs on HMMA bf16 3-term error-compensated split.
// M=64, N=64/CTA, K=1024. grid (16 ntiles, 9 jobs), 256 threads (8 warps).
// Warp w: M-tile (w&3)*16, K-half (w>>2)*512. Stage = k128 slab (64 per half).
// smem/stage: Ah,Al [64][136]bf16 ; Wh,Wl [128][72]bf16
// ---------------------------------------------------------------------------
#define AROW 272                    // bytes (136 bf16)
#define WROW 144                    // bytes (72 bf16)
#define OFF_AH 0
#define OFF_AL 17408
#define OFF_WH 34816
#define OFF_WL 53248
#define STG    71680
#define SMEM_TOTAL (2 * STG)        // 143360 B

__global__ __launch_bounds__(256, 1) void mma_kernel(
    const float* __restrict__ x, const float* __restrict__ h,
    const float* __restrict__ Wi, const float* __restrict__ Wf,
    const float* __restrict__ Wo, const float* __restrict__ Wk,
    const float* __restrict__ Wv, const float* __restrict__ Wq)
{
    extern __shared__ __align__(16) char smem[];
    const uint32_t sb = smem_u32(smem);
    const int tid = threadIdx.x;
    const int wid = tid >> 5;
    const int lane = tid & 31;
    const int job = blockIdx.y;
    const int n0 = blockIdx.x * 64;

    const float *A, *W;
    switch (job) {
        case 0: A = x; W = Wi;                          break;
        case 1: A = h; W = Wi + (size_t)1024 * 1024;    break;
        case 2: A = x; W = Wf;                          break;
        case 3: A = h; W = Wf + (size_t)1024 * 1024;    break;
        case 4: A = x; W = Wo;                          break;
        case 5: A = h; W = Wo + (size_t)1024 * 1024;    break;
        case 6: A = x; W = Wk;                          break;
        case 7: A = x; W = Wv;                          break;
        default: A = h; W = Wq;                         break;
    }
    float* out = g_s[job];

    // ---- gmem load mapping: 256 threads cover A 64x128 and W 128x64 ----
    const int arow = tid >> 2;                   // 0..63 (m)
    const int acb  = (tid & 3) * 32;             // smem col base (k within slab)
    const int akg  = (acb & 63) + ((acb >= 64) ? 512 : 0);  // gmem k base
    const int wrow = tid >> 1;                   // 0..127 (k within slab)
    const int wcb  = (tid & 1) * 32;             // n col base
    const int wkg  = (wrow & 63) + ((wrow >= 64) ? 512 : 0);

    // ---- mma warp mapping ----
    const int mw = wid & 3;
    const int kh = wid >> 2;
    const int m0 = mw * 16;
    const uint32_t a_off = (uint32_t)(m0 + (lane & 15)) * AROW
                         + (uint32_t)((lane >> 4) * 8 + kh * 64) * 2;
    const uint32_t b_off = (uint32_t)((lane & 7) + ((lane >> 3) & 1) * 8 + kh * 64) * WROW
                         + (uint32_t)((lane >> 4) * 8) * 2;

    float acc[8][4] = {};
    float4 pA[8], pW[8];

    // ---- prologue: load chunk 0 ----
    #pragma unroll
    for (int j = 0; j < 8; j++) {
        pA[j] = *(const float4*)(A + (size_t)arow * H_ + akg + j * 4);
        pW[j] = *(const float4*)(W + (size_t)(wkg + wrow % 64 == wrow % 64 ? wkg : wkg) * H_ + n0 + wcb + j * 4);
    }
    // (the W line above is rewritten correctly below; keep single definition)
    #pragma unroll
    for (int j = 0; j < 8; j++)
        pW[j] = *(const float4*)(W + (size_t)wkg * H_ + n0 + wcb + j * 4);
    {
        char* st = smem;
        #pragma unroll
        for (int j = 0; j < 8; j++) {
            uint32_t h0, l0, h1, l1;
            split2(pA[j].x, pA[j].y, h0, l0);
            split2(pA[j].z, pA[j].w, h1, l1);
            const uint32_t ao = (uint32_t)arow * AROW + (uint32_t)(acb + j * 4) * 2;
            *(uint2*)(st + OFF_AH + ao) = make_uint2(h0, h1);
            *(uint2*)(st + OFF_AL + ao) = make_uint2(l0, l1);
            split2(pW[j].x, pW[j].y, h0, l0);
            split2(pW[j].z, pW[j].w, h1, l1);
            const uint32_t wo = (uint32_t)wrow * WROW + (uint32_t)(wcb + j * 4) * 2;
            *(uint2*)(st + OFF_WH + wo) = make_uint2(h0, h1);
            *(uint2*)(st + OFF_WL + wo) = make_uint2(l0, l1);
        }
    }
    __syncthreads();

    #pragma unroll 1
    for (int t = 0; t < 8; t++) {
        const int s = t & 1;

        // prefetch next chunk into registers
        if (t < 7) {
            const int kc = (t + 1) * 64;
            #pragma unroll
            for (int j = 0; j < 8; j++) {
                pA[j] = *(const float4*)(A + (size_t)arow * H_ + kc + akg + j * 4);
                pW[j] = *(const float4*)(W + (size_t)(kc + wkg) * H_ + n0 + wcb + j * 4);
            }
        }

        // compute on stage s (this warp's k64 slab half)
        {
            const uint32_t ah = sb + s * STG + OFF_AH + a_off;
            const uint32_t al = sb + s * STG + OFF_AL + a_off;
            const uint32_t wh = sb + s * STG + OFF_WH + b_off;
            const uint32_t wl = sb + s * STG + OFF_WL + b_off;
            #pragma unroll
            for (int ks = 0; ks < 4; ks++) {
                const uint32_t ko2 = ks * 32;           // k offset bytes (A)
                const uint32_t kor = ks * 16 * WROW;    // k row offset (B)
                uint32_t a0, a1, a2, a3, e0, e1, e2, e3;
                LDSM_X4(a0, a1, a2, a3, ah + ko2);
                LDSM_X4(e0, e1, e2, e3, al + ko2);
                #pragma unroll
                for (int np = 0; np < 4; np++) {
                    const uint32_t no = np * 32;        // n16 -> 16 bf16 = 32B
                    uint32_t b0, b1, b2, b3, f0, f1, f2, f3;
                    LDSM_X4T(b0, b1, b2, b3, wh + kor + no);
                    LDSM_X4T(f0, f1, f2, f3, wl + kor + no);
                    MMA16816(acc[2 * np],     a0, a1, a2, a3, b0, b1);
                    MMA16816(acc[2 * np],     a0, a1, a2, a3, f0, f1);
                    MMA16816(acc[2 * np],     e0, e1, e2, e3, b0, b1);
                    MMA16816(acc[2 * np + 1], a0, a1, a2, a3, b2, b3);
                    MMA16816(acc[2 * np + 1], a0, a1, a2, a3, f2, f3);
                    MMA16816(acc[2 * np + 1], e0, e1, e2, e3, b2, b3);
                }
            }
        }

        // convert + store next chunk into the other stage
        if (t < 7) {
            char* st = smem + (s ^ 1) * STG;
            #pragma unroll
            for (int j = 0; j < 8; j++) {
                uint32_t h0, l0, h1, l1;
                split2(pA[j].x, pA[j].y, h0, l0);
                split2(pA[j].z, pA[j].w, h1, l1);
                const uint32_t ao = (uint32_t)arow * AROW + (uint32_t)(acb + j * 4) * 2;
                *(uint2*)(st + OFF_AH + ao) = make_uint2(h0, h1);
                *(uint2*)(st + OFF_AL + ao) = make_uint2(l0, l1);
                split2(pW[j].x, pW[j].y, h0, l0);
                split2(pW[j].z, pW[j].w, h1, l1);
                const uint32_t wo = (uint32_t)wrow * WROW + (uint32_t)(wcb + j * 4) * 2;
                *(uint2*)(st + OFF_WH + wo) = make_uint2(h0, h1);
                *(uint2*)(st + OFF_WL + wo) = make_uint2(l0, l1);
            }
        }
        __syncthreads();
    }

    // ---- cross-K-half reduction (kh=1 -> smem, kh=0 adds) ----
    __syncthreads();
    if (kh == 1) {
        float* red = (float*)(smem + ((mw * 32 + lane) * 32) * 4);
        #pragma unroll
        for (int na = 0; na < 8; na++)
            *(float4*)(red + na * 4) = make_float4(acc[na][0], acc[na][1],
                                                   acc[na][2], acc[na][3]);
    }
    __syncthreads();
    if (kh == 0) {
        const float* red = (const float*)(smem + ((mw * 32 + lane) * 32) * 4);
        const int r0 = m0 + (lane >> 2);
        const int c0 = (lane & 3) * 2;
        #pragma unroll
        for (int na = 0; na < 8; na++) {
            float4 o = *(const float4*)(red + na * 4);
            *(float2*)(out + (size_t)r0 * H_ + n0 + na * 8 + c0) =
                make_float2(acc[na][0] + o.x, acc[na][1] + o.y);
            *(float2*)(out + (size_t)(r0 + 8) * H_ + n0 + na * 8 + c0) =
                make_float2(acc[na][2] + o.z, acc[na][3] + o.w);
        }
    }
}

// ---------------------------------------------------------------------------
// Kernel 2: e partials. A = (g_s[6] + bk) [64,1024], W = We. split-K=8.
// ---------------------------------------------------------------------------
__global__ __launch_bounds__(256, 1) void egemm_kernel(
    const float* __restrict__ We, const float* __restrict__ bk)
{
    constexpr int TK = 32;
    __shared__ __align__(16) float As[2][TK][64 + 4];
    __shared__ __align__(16) float Ws[2][TK][64 + 4];

    const float* A0 = &g_s[6][0];
    float* out = &g_ep[blockIdx.y][0];
    const int kbase = blockIdx.y * 128;
    const int n0 = blockIdx.x * 64;
    const int t  = threadIdx.x;
    const int tr = t >> 4;
    const int tc = t & 15;

    const int arow = t >> 3;
    const int akq  = (t & 7) << 2;
    const int wr   = t >> 4;
    const int wc   = (t & 15) << 2;

    float acc[4][4] = {};
    float4 pa0, pa1, pw0, pw1, pb;

    pa0 = *(const float4*)(A0 + arow * H_ + kbase + akq);
    pa1 = *(const float4*)(A0 + (arow + 32) * H_ + kbase + akq);
    pb  = *(const float4*)(bk + kbase + akq);
    pw0 = *(const float4*)(We + (size_t)(kbase + wr) * H_ + n0 + wc);
    pw1 = *(const float4*)(We + (size_t)(kbase + wr + 16) * H_ + n0 + wc);
    As[0][akq + 0][arow] = pa0.x + pb.x;  As[0][akq + 1][arow] = pa0.y + pb.y;
    As[0][akq + 2][arow] = pa0.z + pb.z;  As[0][akq + 3][arow] = pa0.w + pb.w;
    As[0][akq + 0][arow + 32] = pa1.x + pb.x;  As[0][akq + 1][arow + 32] = pa1.y + pb.y;
    As[0][akq + 2][arow + 32] = pa1.z + pb.z;  As[0][akq + 3][arow + 32] = pa1.w + pb.w;
    *(float4*)&Ws[0][wr][wc]      = pw0;
    *(float4*)&Ws[0][wr + 16][wc] = pw1;
    __syncthreads();

    #pragma unroll 1
    for (int tile = 0; tile < 4; tile++) {
        const int cur = tile & 1;
        const int nxt = cur ^ 1;
        if (tile + 1 < 4) {
            const int k0n = kbase + (tile + 1) * TK;
            pa0 = *(const float4*)(A0 + arow * H_ + k0n + akq);
            pa1 = *(const float4*)(A0 + (arow + 32) * H_ + k0n + akq);
            pb  = *(const float4*)(bk + k0n + akq);
            pw0 = *(const float4*)(We + (size_t)(k0n + wr) * H_ + n0 + wc);
            pw1 = *(const float4*)(We + (size_t)(k0n + wr + 16) * H_ + n0 + wc);
        }
        #pragma unroll
        for (int kk = 0; kk < TK; kk++) {
            float4 a = *(const float4*)&As[cur][kk][tr << 2];
            float4 b = *(const float4*)&Ws[cur][kk][tc << 2];
            #pragma unroll
            for (int i = 0; i < 4; i++) {
                float av = (i == 0) ? a.x : (i == 1) ? a.y : (i == 2) ? a.z : a.w;
                acc[i][0] = fmaf(av, b.x, acc[i][0]);
                acc[i][1] = fmaf(av, b.y, acc[i][1]);
                acc[i][2] = fmaf(av, b.z, acc[i][2]);
                acc[i][3] = fmaf(av, b.w, acc[i][3]);
            }
        }
        if (tile + 1 < 4) {
            As[nxt][akq + 0][arow] = pa0.x + pb.x;  As[nxt][akq + 1][arow] = pa0.y + pb.y;
            As[nxt][akq + 2][arow] = pa0.z + pb.z;  As[nxt][akq + 3][arow] = pa0.w + pb.w;
            As[nxt][akq + 0][arow + 32] = pa1.x + pb.x;  As[nxt][akq + 1][arow + 32] = pa1.y + pb.y;
            As[nxt][akq + 2][arow + 32] = pa1.z + pb.z;  As[nxt][akq + 3][arow + 32] = pa1.w + pb.w;
            *(float4*)&Ws[nxt][wr][wc]      = pw0;
            *(float4*)&Ws[nxt][wr + 16][wc] = pw1;
        }
        __syncthreads();
    }

    #pragma unroll
    for (int i = 0; i < 4; i++) {
        int row = (tr << 2) + i;
        float4 v = make_float4(acc[i][0], acc[i][1], acc[i][2], acc[i][3]);
        *(float4*)(out + row * H_ + n0 + (tc << 2)) = v;
    }
}

// ---------------------------------------------------------------------------
// Kernel 3: C-stream update (HBM roofline pass)
// ---------------------------------------------------------------------------
__device__ __forceinline__ float sigmoidf_(float z) {
    return 1.0f / (1.0f + expf(-z));
}

__global__ __launch_bounds__(256, 8) void update_kernel(
    const float* __restrict__ C_prev, const float* __restrict__ n_prev,
    const float* __restrict__ bi, const float* __restrict__ bf,
    const float* __restrict__ bo, const float* __restrict__ bk,
    const float* __restrict__ bv, const float* __restrict__ bq,
    const float* __restrict__ be,
    float* __restrict__ out_h, float* __restrict__ out_C,
    float* __restrict__ out_n)
{
    __shared__ __align__(16) float ks[H_];
    __shared__ __align__(16) float qs[H_];

    const int b    = blockIdx.y;
    const int r0   = blockIdx.x * 8;
    const int t    = threadIdx.x;
    const int w    = t >> 5;
    const int lane = t & 31;

    {
        int c = t << 2;
        float4 k0 = *(const float4*)(&g_s[6][b * H_] + c);
        float4 bkv = *(const float4*)(bk + c);
        float4 q0 = *(const float4*)(&g_s[8][b * H_] + c);
        float4 bqv = *(const float4*)(bq + c);
        *(float4*)&ks[c] = make_float4(k0.x + bkv.x, k0.y + bkv.y,
                                       k0.z + bkv.z, k0.w + bkv.w);
        *(float4*)&qs[c] = make_float4(q0.x + bqv.x, q0.y + bqv.y,
                                       q0.z + bqv.z, q0.w + bqv.w);
    }
    __syncthreads();

    const int r = r0 + w;
    const int br = b * H_ + r;

    const float it = sigmoidf_(g_s[0][br] + g_s[1][br] + bi[r]);
    const float ft = sigmoidf_(g_s[2][br] + g_s[3][br] + bf[r]);
    const float ot = sigmoidf_(g_s[4][br] + g_s[5][br] + bo[r]);
    const float vt = g_s[7][br] + bv[r];
    const float iv = it * vt;

    const size_t base = (size_t)b * H_ * H_ + (size_t)r * H_;
    float dot = 0.0f;

    #pragma unroll
    for (int it8 = 0; it8 < 8; it8++) {
        int c = (lane << 2) + (it8 << 7);
        float4 cp = __ldcs((const float4*)(C_prev + base + c));
        float4 kv = *(const float4*)&ks[c];
        float4 qv = *(const float4*)&qs[c];
        float4 ct;
        ct.x = fmaf(ft, cp.x, iv * kv.x);
        ct.y = fmaf(ft, cp.y, iv * kv.y);
        ct.z = fmaf(ft, cp.z, iv * kv.z);
        ct.w = fmaf(ft, cp.w, iv * kv.w);
        __stcs((float4*)(out_C + base + c), ct);
        dot = fmaf(ct.x, qv.x, dot);
        dot = fmaf(ct.y, qv.y, dot);
        dot = fmaf(ct.z, qv.z, dot);
        dot = fmaf(ct.w, qv.w, dot);
    }

    #pragma unroll
    for (int off = 16; off; off >>= 1)
        dot += __shfl_xor_sync(0xffffffffu, dot, off);

    if (lane == 0) {
        float e = be[r];
        #pragma unroll
        for (int p = 0; p < 8; p++) e += g_ep[p][br];
        float nt = fmaf(ft, n_prev[br], it * expf(e));
        out_n[br] = nt;
        out_h[br] = ot * dot / nt;
    }
}

// ---------------------------------------------------------------------------
extern "C" void kernel_launch(void* const* d_in, const int* in_sizes, int n_in,
                              void* d_out, int out_size)
{
    const float* x      = (const float*)d_in[0];
    const float* h_prev = (const float*)d_in[1];
    const float* C_prev = (const float*)d_in[2];
    const float* n_prev = (const float*)d_in[3];
    const float* Wi = (const float*)d_in[4];
    const float* bi = (const float*)d_in[5];
    const float* Wf = (const float*)d_in[6];
    const float* bf = (const float*)d_in[7];
    const float* Wo = (const float*)d_in[8];
    const float* bo = (const float*)d_in[9];
    const float* Wk = (const float*)d_in[10];
    const float* bk = (const float*)d_in[11];
    const float* Wv = (const float*)d_in[12];
    const float* bv = (const float*)d_in[13];
    const float* Wq = (const float*)d_in[14];
    const float* bq = (const float*)d_in[15];
    const float* We = (const float*)d_in[16];
    const float* be = (const float*)d_in[17];

    float* out_h = (float*)d_out;
    float* out_C = out_h + B_ * H_;
    float* out_n = out_C + (size_t)B_ * H_ * H_;

    static int smem_set = 0;
    if (!smem_set) {
        cudaFuncSetAttribute(mma_kernel, cudaFuncAttributeMaxDynamicSharedMemorySize,
                             SMEM_TOTAL);
        smem_set = 1;
    }

    mma_kernel<<<dim3(16, 9), 256, SMEM_TOTAL>>>(x, h_prev, Wi, Wf, Wo, Wk, Wv, Wq);
    egemm_kernel<<<dim3(16, 8), 256>>>(We, bk);
    update_kernel<<<dim3(128, 64), 256>>>(C_prev, n_prev, bi, bf, bo, bk, bv, bq, be,
                                          out_h, out_C, out_n);
}